// round 12
// baseline (speedup 1.0000x reference)
#include <cuda_runtime.h>

// Problem constants
#define NCH   8192
#define NTT   4096
#define NLAGS 103
#define RAWS  112
#define XCOR_N (NCH * NLAGS)

// Stage-1: each block does ONE t-half (2048 t) of one channel.
// 4 warps/block; exact lag split {26,26,26,25}, bases {0,26,52,78}.
// a_sm2[j] = d1[G0 + j], G0 = 2048*h - 64  (zero outside [0,NTT)).
// d1pad[2048h + i] = a_sm2[i + 13]; per-slot aligned base B=(lb+13)&~3,
// compile-time window offset OFF=(lb+13)&3.
#define T1     128
#define A_SZ2  2240          // floats in a_sm2 (560 float4 chunks)
#define B_SZ2  2048
#define SMEM1  ((A_SZ2 + B_SZ2) * 4)   // 17152 B

// Two half-sum scratch buffers (no atomics; stage2 adds them). ~7.3 MB, L2-resident.
__device__ float g_raw[2][(size_t)NCH * RAWS];

// ---------------------------------------------------------------------------
// Per-warp correlation over one t-half: L lags, compile-time offset OFF from
// the 16B-aligned base a_al. Lane handles 4 consecutive t; 16 iters = 2048 t.
// acc[j] += a_al[t_local + OFF + j + k] * b[t_local + k]
// ---------------------------------------------------------------------------
template<int L, int OFF>
__device__ __forceinline__ void corr_warp(const float* __restrict__ a_al,
                                          const float* __restrict__ b_sm,
                                          int lane,
                                          float* __restrict__ outRow)
{
    constexpr int NV = (OFF + L + 3 + 3) / 4;   // float4 loads covering window

    float acc[L];
#pragma unroll
    for (int j = 0; j < L; ++j) acc[j] = 0.0f;

#pragma unroll 1
    for (int it = 0; it < 16; ++it) {
        const int t0 = it * 128 + lane * 4;

        float aw[NV * 4];
#pragma unroll
        for (int v = 0; v < NV; ++v) {
            const float4 w = *reinterpret_cast<const float4*>(a_al + t0 + 4 * v);
            aw[4 * v + 0] = w.x; aw[4 * v + 1] = w.y;
            aw[4 * v + 2] = w.z; aw[4 * v + 3] = w.w;
        }
        const float4 b4 = *reinterpret_cast<const float4*>(b_sm + t0);
        float bv[4];
        bv[0] = b4.x; bv[1] = b4.y; bv[2] = b4.z; bv[3] = b4.w;

#pragma unroll
        for (int k = 0; k < 4; ++k) {
#pragma unroll
            for (int j = 0; j < L; ++j) {
                acc[j] = fmaf(aw[OFF + j + k], bv[k], acc[j]);
            }
        }
    }

    // Lane reduction over t; lane 0 writes L lags.
#pragma unroll
    for (int j = 0; j < L; ++j) {
#pragma unroll
        for (int o = 16; o > 0; o >>= 1)
            acc[j] += __shfl_xor_sync(0xffffffffu, acc[j], o);
    }
    if (lane == 0) {
#pragma unroll
        for (int j = 0; j < L; ++j) outRow[j] = acc[j];
    }
}

// ---------------------------------------------------------------------------
// Stage 1: partial R_h[c][l] = sum_{t in half h} d1pad[t+l] * d2[t].
// blockIdx.x = channel, blockIdx.y = half. Slot -> (lb, L, B, OFF):
//   0: lb=0,  L=26, B=12, OFF=1
//   1: lb=26, L=26, B=36, OFF=3
//   2: lb=52, L=26, B=64, OFF=1
//   3: lb=78, L=25, B=88, OFF=3
// ---------------------------------------------------------------------------
__global__ __launch_bounds__(T1, 6)
void xcorr_stage1(const float* __restrict__ d1, const float* __restrict__ d2)
{
    extern __shared__ __align__(16) float sm[];
    float* a_sm = sm;            // [A_SZ2]
    float* b_sm = sm + A_SZ2;    // [B_SZ2]

    const int c   = blockIdx.x;
    const int h   = blockIdx.y;
    const int tid = threadIdx.x;

    const float4* __restrict__ r1_4 = reinterpret_cast<const float4*>(d1 + (size_t)c * NTT);
    const float4* __restrict__ r2_4 = reinterpret_cast<const float4*>(d2 + (size_t)c * NTT);

    // a_sm[4k..4k+3] = d1[G0+4k .. +3], G0 = 2048h - 64; zero outside [0,NTT).
    const int g4base = 512 * h - 16;       // G0/4
    for (int k = tid; k < A_SZ2 / 4; k += T1) {
        const int g4 = g4base + k;
        reinterpret_cast<float4*>(a_sm)[k] =
            (g4 >= 0 && g4 < NTT / 4) ? r1_4[g4] : make_float4(0.f, 0.f, 0.f, 0.f);
    }
    // b_sm = d2[2048h .. 2048h+2048)
    for (int k = tid; k < B_SZ2 / 4; k += T1) {
        reinterpret_cast<float4*>(b_sm)[k] = r2_4[512 * h + k];
    }
    __syncthreads();

    const int warp = tid >> 5;
    const int lane = tid & 31;
    // Rotate slot assignment across blocks for SMSP load balance.
    const int slot = (warp + c + h) & 3;

    float* row = g_raw[h] + (size_t)c * RAWS;
    switch (slot) {
        case 0: corr_warp<26, 1>(a_sm + 12, b_sm, lane, row + 0);  break;
        case 1: corr_warp<26, 3>(a_sm + 36, b_sm, lane, row + 26); break;
        case 2: corr_warp<26, 1>(a_sm + 64, b_sm, lane, row + 52); break;
        default: corr_warp<25, 3>(a_sm + 88, b_sm, lane, row + 78); break;
    }
}

// ---------------------------------------------------------------------------
// Stage 2: sum the two halves, moving average over channels (window
// [c-10, c+9], zero-padded), then per-channel argmax|R| / max / min / tmax.
// 8 channels per block; 27 halo values prefetched into registers (MLP).
// ---------------------------------------------------------------------------
#define CPB 8
__global__ __launch_bounds__(128)
void xcorr_stage2(float* __restrict__ out)
{
    __shared__ float sh[CPB][NLAGS + 1];
    const int c0  = blockIdx.x * CPB;
    const int tid = threadIdx.x;

    if (tid < NLAGS) {
        float x[CPB + 19];
#pragma unroll
        for (int i = 0; i < CPB + 19; ++i) {
            const int ch = c0 - 10 + i;
            x[i] = (ch >= 0 && ch < NCH)
                 ? (g_raw[0][(size_t)ch * RAWS + tid] + g_raw[1][(size_t)ch * RAWS + tid])
                 : 0.0f;
        }
        float s = 0.0f;
#pragma unroll
        for (int i = 0; i < 20; ++i) s += x[i];
#pragma unroll
        for (int cc = 0; cc < CPB; ++cc) {
            const float m = s * (1.0f / 20.0f);
            sh[cc][tid] = m;
            out[(size_t)(c0 + cc) * NLAGS + tid] = m;
            if (cc + 1 < CPB) s += x[cc + 20] - x[cc];
        }
    }
    __syncthreads();

    const int warp = tid >> 5;
    const int lane = tid & 31;

    for (int cc = warp; cc < CPB; cc += 4) {
        float bestAbs = -1.0f;
        int   bestIdx = 0;
        float bestVal = 0.0f;
        float vpos = -3.402823466e38f;
        float vneg =  3.402823466e38f;

        for (int l = lane; l < NLAGS; l += 32) {
            const float v  = sh[cc][l];
            const float av = fabsf(v);
            if (av > bestAbs) { bestAbs = av; bestIdx = l; bestVal = v; }
            vpos = fmaxf(vpos, v);
            vneg = fminf(vneg, v);
        }
#pragma unroll
        for (int o = 16; o > 0; o >>= 1) {
            const float oa = __shfl_down_sync(0xffffffffu, bestAbs, o);
            const int   oi = __shfl_down_sync(0xffffffffu, bestIdx, o);
            const float ov = __shfl_down_sync(0xffffffffu, bestVal, o);
            if (oa > bestAbs || (oa == bestAbs && oi < bestIdx)) {
                bestAbs = oa; bestIdx = oi; bestVal = ov;
            }
            vpos = fmaxf(vpos, __shfl_down_sync(0xffffffffu, vpos, o));
            vneg = fminf(vneg, __shfl_down_sync(0xffffffffu, vneg, o));
        }

        if (lane == 0) {
            const int   ch    = c0 + cc;
            const float vside = (bestVal >= 0.0f) ? vneg : vpos;
            out[(size_t)XCOR_N + ch]           = bestVal;
            out[(size_t)XCOR_N + NCH + ch]     = vside;
            out[(size_t)XCOR_N + 2 * NCH + ch] = (float)(bestIdx - 51) * 0.01f;
        }
    }
}

// ---------------------------------------------------------------------------
// kernel_launch: inputs: data1 (f32, NC*NT), data2 (f32, NC*NT), event1,
// event2 (i32, unused by the reference).
// ---------------------------------------------------------------------------
extern "C" void kernel_launch(void* const* d_in, const int* in_sizes, int n_in,
                              void* d_out, int out_size)
{
    const float* data1 = (const float*)d_in[0];
    const float* data2 = (const float*)d_in[1];
    float* out = (float*)d_out;

    dim3 grid1(NCH, 2);
    xcorr_stage1<<<grid1, T1, SMEM1>>>(data1, data2);
    xcorr_stage2<<<NCH / CPB, 128>>>(out);
}

// round 13
// speedup vs baseline: 1.1789x; 1.1789x over previous
#include <cuda_runtime.h>

// Problem constants
#define NCH   8192
#define NTT   4096
#define NLAGS 103
#define RAWS  112
#define XCOR_N (NCH * NLAGS)

// Stage-1: 4 warps/block; exact lag split {26,26,26,25}, bases {0,26,52,78}.
// d1 stored UNshifted at float offset 64 => d1pad[x] = a_sm[x + 13].
// Per-slot aligned window base B=(lb+13)&~3, compile-time offset OFF=(lb+13)&3.
#define T1     128
#define A_OFF  64            // where d1[0] lands in a_sm (16B aligned)
#define A_SZ   4224          // covers max read index 4211
#define SMEM1  ((A_SZ + NTT) * 4)

// Raw xcorr scratch: 8192 x 112 f32 (~3.67 MB, L2-resident)
__device__ float g_raw[(size_t)NCH * RAWS];

// ---------------------------------------------------------------------------
// Per-warp correlation: L lags, window offset OFF from the aligned base a_al.
// Lane handles 4 consecutive t per iter; 32 iters cover 4096 t.
// acc[j] = sum_t a_al[t + OFF + j + k] * b[t + k]  (k = 0..3 within the iter)
// ---------------------------------------------------------------------------
template<int L, int OFF>
__device__ __forceinline__ void corr_warp(const float* __restrict__ a_al,
                                          const float* __restrict__ b_sm,
                                          int lane,
                                          float* __restrict__ outRow)
{
    constexpr int NV = (OFF + L + 3 + 3) / 4;   // float4 loads covering window

    float acc[L];
#pragma unroll
    for (int j = 0; j < L; ++j) acc[j] = 0.0f;

#pragma unroll 2
    for (int it = 0; it < 32; ++it) {
        const int t0 = it * 128 + lane * 4;

        float aw[NV * 4];
#pragma unroll
        for (int v = 0; v < NV; ++v) {
            const float4 w = *reinterpret_cast<const float4*>(a_al + t0 + 4 * v);
            aw[4 * v + 0] = w.x; aw[4 * v + 1] = w.y;
            aw[4 * v + 2] = w.z; aw[4 * v + 3] = w.w;
        }
        const float4 b4 = *reinterpret_cast<const float4*>(b_sm + t0);
        float bv[4];
        bv[0] = b4.x; bv[1] = b4.y; bv[2] = b4.z; bv[3] = b4.w;

#pragma unroll
        for (int k = 0; k < 4; ++k) {
#pragma unroll
            for (int j = 0; j < L; ++j) {
                acc[j] = fmaf(aw[OFF + j + k], bv[k], acc[j]);
            }
        }
    }

    // Lane reduction over t; lane 0 writes L lags.
#pragma unroll
    for (int j = 0; j < L; ++j) {
#pragma unroll
        for (int o = 16; o > 0; o >>= 1)
            acc[j] += __shfl_xor_sync(0xffffffffu, acc[j], o);
    }
    if (lane == 0) {
#pragma unroll
        for (int j = 0; j < L; ++j) outRow[j] = acc[j];
    }
}

// ---------------------------------------------------------------------------
// Stage 1: R[c][l] = sum_t d1pad[t+l] * d2[t], l in [0,103), with
// d1pad[x] = d1[x-51] (zero outside). One block per channel, 128 threads.
// Slot -> (lag base lb, L, aligned base B=(lb+13)&~3, OFF=(lb+13)&3):
//   0: lb=0,  L=26, B=12, OFF=1
//   1: lb=26, L=26, B=36, OFF=3
//   2: lb=52, L=26, B=64, OFF=1
//   3: lb=78, L=25, B=88, OFF=3
// ---------------------------------------------------------------------------
__global__ __launch_bounds__(T1, 6)
void xcorr_stage1(const float* __restrict__ d1, const float* __restrict__ d2)
{
    extern __shared__ __align__(16) float sm[];
    float* a_sm = sm;            // [A_SZ]; d1 at [A_OFF, A_OFF+NTT)
    float* b_sm = sm + A_SZ;     // [NTT]

    const int c   = blockIdx.x;
    const int tid = threadIdx.x;

    const float* __restrict__ r1 = d1 + (size_t)c * NTT;
    const float* __restrict__ r2 = d2 + (size_t)c * NTT;

    // Zero pads: [0, A_OFF) and [A_OFF+NTT, A_SZ)
    for (int i = tid; i < A_OFF / 4; i += T1)
        reinterpret_cast<float4*>(a_sm)[i] = make_float4(0.f, 0.f, 0.f, 0.f);
    for (int i = tid; i < (A_SZ - A_OFF - NTT) / 4; i += T1)
        reinterpret_cast<float4*>(a_sm + A_OFF + NTT)[i] = make_float4(0.f, 0.f, 0.f, 0.f);

    // Bulk fill: pure float4 loads and stores (a unshifted at offset 64).
    for (int k = tid; k < NTT / 4; k += T1) {
        reinterpret_cast<float4*>(a_sm + A_OFF)[k] = reinterpret_cast<const float4*>(r1)[k];
        reinterpret_cast<float4*>(b_sm)[k]         = reinterpret_cast<const float4*>(r2)[k];
    }
    __syncthreads();

    const int warp = tid >> 5;
    const int lane = tid & 31;
    // Rotate slot assignment across blocks for SMSP load balance.
    const int slot = (warp + blockIdx.x) & 3;

    float* row = g_raw + (size_t)c * RAWS;
    switch (slot) {
        case 0: corr_warp<26, 1>(a_sm + 12, b_sm, lane, row + 0);  break;
        case 1: corr_warp<26, 3>(a_sm + 36, b_sm, lane, row + 26); break;
        case 2: corr_warp<26, 1>(a_sm + 64, b_sm, lane, row + 52); break;
        default: corr_warp<25, 3>(a_sm + 88, b_sm, lane, row + 78); break;
    }
}

// ---------------------------------------------------------------------------
// Stage 2: moving average over channels (window [c-10, c+9], zero-padded),
// then per-channel argmax|R| / max / min / tmax.
// 8 channels per block; each thread prefetches all 27 halo values (MLP) then
// computes the sliding sum in registers (no serial L2 chain).
// ---------------------------------------------------------------------------
#define CPB 8
__global__ __launch_bounds__(128)
void xcorr_stage2(float* __restrict__ out)
{
    __shared__ float sh[CPB][NLAGS + 1];
    const int c0  = blockIdx.x * CPB;
    const int tid = threadIdx.x;

    if (tid < NLAGS) {
        float x[CPB + 19];
#pragma unroll
        for (int i = 0; i < CPB + 19; ++i) {
            const int ch = c0 - 10 + i;
            x[i] = (ch >= 0 && ch < NCH) ? g_raw[(size_t)ch * RAWS + tid] : 0.0f;
        }
        float s = 0.0f;
#pragma unroll
        for (int i = 0; i < 20; ++i) s += x[i];
#pragma unroll
        for (int cc = 0; cc < CPB; ++cc) {
            const float m = s * (1.0f / 20.0f);
            sh[cc][tid] = m;
            out[(size_t)(c0 + cc) * NLAGS + tid] = m;
            if (cc + 1 < CPB) s += x[cc + 20] - x[cc];
        }
    }
    __syncthreads();

    const int warp = tid >> 5;
    const int lane = tid & 31;

    for (int cc = warp; cc < CPB; cc += 4) {
        float bestAbs = -1.0f;
        int   bestIdx = 0;
        float bestVal = 0.0f;
        float vpos = -3.402823466e38f;
        float vneg =  3.402823466e38f;

        for (int l = lane; l < NLAGS; l += 32) {
            const float v  = sh[cc][l];
            const float av = fabsf(v);
            if (av > bestAbs) { bestAbs = av; bestIdx = l; bestVal = v; }
            vpos = fmaxf(vpos, v);
            vneg = fminf(vneg, v);
        }
#pragma unroll
        for (int o = 16; o > 0; o >>= 1) {
            const float oa = __shfl_down_sync(0xffffffffu, bestAbs, o);
            const int   oi = __shfl_down_sync(0xffffffffu, bestIdx, o);
            const float ov = __shfl_down_sync(0xffffffffu, bestVal, o);
            if (oa > bestAbs || (oa == bestAbs && oi < bestIdx)) {
                bestAbs = oa; bestIdx = oi; bestVal = ov;
            }
            vpos = fmaxf(vpos, __shfl_down_sync(0xffffffffu, vpos, o));
            vneg = fminf(vneg, __shfl_down_sync(0xffffffffu, vneg, o));
        }

        if (lane == 0) {
            const int   ch    = c0 + cc;
            const float vside = (bestVal >= 0.0f) ? vneg : vpos;
            out[(size_t)XCOR_N + ch]           = bestVal;
            out[(size_t)XCOR_N + NCH + ch]     = vside;
            out[(size_t)XCOR_N + 2 * NCH + ch] = (float)(bestIdx - 51) * 0.01f;
        }
    }
}

// ---------------------------------------------------------------------------
// kernel_launch: inputs: data1 (f32, NC*NT), data2 (f32, NC*NT), event1,
// event2 (i32, unused by the reference).
// ---------------------------------------------------------------------------
extern "C" void kernel_launch(void* const* d_in, const int* in_sizes, int n_in,
                              void* d_out, int out_size)
{
    const float* data1 = (const float*)d_in[0];
    const float* data2 = (const float*)d_in[1];
    float* out = (float*)d_out;

    xcorr_stage1<<<NCH, T1, SMEM1>>>(data1, data2);
    xcorr_stage2<<<NCH / CPB, 128>>>(out);
}

// round 14
// speedup vs baseline: 1.1822x; 1.0028x over previous
#include <cuda_runtime.h>

// Problem constants
#define NCH   8192
#define NTT   4096
#define NLAGS 103
#define RAWS  112
#define XCOR_N (NCH * NLAGS)

// Stage-1: 4 warps/block; exact lag split {26,26,26,25}, bases {0,26,52,78}.
// d1 stored UNshifted at float offset 64 => d1pad[x] = a_sm[x + 13].
// Per-slot aligned window base B=(lb+13)&~3, compile-time offset OFF=(lb+13)&3.
#define T1     128
#define A_OFF  64            // where d1[0] lands in a_sm (16B aligned)
#define A_SZ   4224          // covers max read index 4211
#define SMEM1  ((A_SZ + NTT) * 4)

// Raw xcorr scratch: 8192 x 112 f32 (~3.67 MB, L2-resident)
__device__ float g_raw[(size_t)NCH * RAWS];

// ---------------------------------------------------------------------------
// Per-warp correlation: L lags, window offset OFF from the aligned base a_al.
// Lane handles 4 consecutive t per iter; 32 iters cover 4096 t.
// acc[j] = sum_t a_al[t + OFF + j + k] * b[t + k]  (k = 0..3 within the iter)
// ---------------------------------------------------------------------------
template<int L, int OFF>
__device__ __forceinline__ void corr_warp(const float* __restrict__ a_al,
                                          const float* __restrict__ b_sm,
                                          int lane,
                                          float* __restrict__ outRow)
{
    constexpr int NV = (OFF + L + 3 + 3) / 4;   // float4 loads covering window

    float acc[L];
#pragma unroll
    for (int j = 0; j < L; ++j) acc[j] = 0.0f;

#pragma unroll 1
    for (int it = 0; it < 32; ++it) {
        const int t0 = it * 128 + lane * 4;

        float aw[NV * 4];
#pragma unroll
        for (int v = 0; v < NV; ++v) {
            const float4 w = *reinterpret_cast<const float4*>(a_al + t0 + 4 * v);
            aw[4 * v + 0] = w.x; aw[4 * v + 1] = w.y;
            aw[4 * v + 2] = w.z; aw[4 * v + 3] = w.w;
        }
        const float4 b4 = *reinterpret_cast<const float4*>(b_sm + t0);
        float bv[4];
        bv[0] = b4.x; bv[1] = b4.y; bv[2] = b4.z; bv[3] = b4.w;

#pragma unroll
        for (int k = 0; k < 4; ++k) {
#pragma unroll
            for (int j = 0; j < L; ++j) {
                acc[j] = fmaf(aw[OFF + j + k], bv[k], acc[j]);
            }
        }
    }

    // Lane reduction over t; lane 0 writes L lags.
#pragma unroll
    for (int j = 0; j < L; ++j) {
#pragma unroll
        for (int o = 16; o > 0; o >>= 1)
            acc[j] += __shfl_xor_sync(0xffffffffu, acc[j], o);
    }
    if (lane == 0) {
#pragma unroll
        for (int j = 0; j < L; ++j) outRow[j] = acc[j];
    }
}

// ---------------------------------------------------------------------------
// Stage 1: R[c][l] = sum_t d1pad[t+l] * d2[t], l in [0,103), with
// d1pad[x] = d1[x-51] (zero outside). One block per channel, 128 threads.
// Slot -> (lag base lb, L, aligned base B=(lb+13)&~3, OFF=(lb+13)&3):
//   0: lb=0,  L=26, B=12, OFF=1
//   1: lb=26, L=26, B=36, OFF=3
//   2: lb=52, L=26, B=64, OFF=1
//   3: lb=78, L=25, B=88, OFF=3
// ---------------------------------------------------------------------------
__global__ __launch_bounds__(T1, 6)
void xcorr_stage1(const float* __restrict__ d1, const float* __restrict__ d2)
{
    extern __shared__ __align__(16) float sm[];
    float* a_sm = sm;            // [A_SZ]; d1 at [A_OFF, A_OFF+NTT)
    float* b_sm = sm + A_SZ;     // [NTT]

    const int c   = blockIdx.x;
    const int tid = threadIdx.x;

    const float* __restrict__ r1 = d1 + (size_t)c * NTT;
    const float* __restrict__ r2 = d2 + (size_t)c * NTT;

    // Zero pads: [0, A_OFF) and [A_OFF+NTT, A_SZ)
    for (int i = tid; i < A_OFF / 4; i += T1)
        reinterpret_cast<float4*>(a_sm)[i] = make_float4(0.f, 0.f, 0.f, 0.f);
    for (int i = tid; i < (A_SZ - A_OFF - NTT) / 4; i += T1)
        reinterpret_cast<float4*>(a_sm + A_OFF + NTT)[i] = make_float4(0.f, 0.f, 0.f, 0.f);

    // Bulk fill: pure float4 loads and stores (a unshifted at offset 64).
    for (int k = tid; k < NTT / 4; k += T1) {
        reinterpret_cast<float4*>(a_sm + A_OFF)[k] = reinterpret_cast<const float4*>(r1)[k];
        reinterpret_cast<float4*>(b_sm)[k]         = reinterpret_cast<const float4*>(r2)[k];
    }
    __syncthreads();

    const int warp = tid >> 5;
    const int lane = tid & 31;
    // Rotate slot assignment across blocks for SMSP load balance.
    const int slot = (warp + blockIdx.x) & 3;

    float* row = g_raw + (size_t)c * RAWS;
    switch (slot) {
        case 0: corr_warp<26, 1>(a_sm + 12, b_sm, lane, row + 0);  break;
        case 1: corr_warp<26, 3>(a_sm + 36, b_sm, lane, row + 26); break;
        case 2: corr_warp<26, 1>(a_sm + 64, b_sm, lane, row + 52); break;
        default: corr_warp<25, 3>(a_sm + 88, b_sm, lane, row + 78); break;
    }
}

// ---------------------------------------------------------------------------
// Stage 2: moving average over channels (window [c-10, c+9], zero-padded),
// then per-channel argmax|R| / max / min / tmax.
// 16 channels per block; each thread prefetches all 35 halo values (MLP) then
// computes the sliding sum in registers (no serial L2 chain).
// ---------------------------------------------------------------------------
#define CPB 16
__global__ __launch_bounds__(128)
void xcorr_stage2(float* __restrict__ out)
{
    __shared__ float sh[CPB][NLAGS + 1];
    const int c0  = blockIdx.x * CPB;
    const int tid = threadIdx.x;

    if (tid < NLAGS) {
        float x[CPB + 19];
#pragma unroll
        for (int i = 0; i < CPB + 19; ++i) {
            const int ch = c0 - 10 + i;
            x[i] = (ch >= 0 && ch < NCH) ? g_raw[(size_t)ch * RAWS + tid] : 0.0f;
        }
        float s = 0.0f;
#pragma unroll
        for (int i = 0; i < 20; ++i) s += x[i];
#pragma unroll
        for (int cc = 0; cc < CPB; ++cc) {
            const float m = s * (1.0f / 20.0f);
            sh[cc][tid] = m;
            out[(size_t)(c0 + cc) * NLAGS + tid] = m;
            if (cc + 1 < CPB) s += x[cc + 20] - x[cc];
        }
    }
    __syncthreads();

    const int warp = tid >> 5;
    const int lane = tid & 31;

    for (int cc = warp; cc < CPB; cc += 4) {
        float bestAbs = -1.0f;
        int   bestIdx = 0;
        float bestVal = 0.0f;
        float vpos = -3.402823466e38f;
        float vneg =  3.402823466e38f;

        for (int l = lane; l < NLAGS; l += 32) {
            const float v  = sh[cc][l];
            const float av = fabsf(v);
            if (av > bestAbs) { bestAbs = av; bestIdx = l; bestVal = v; }
            vpos = fmaxf(vpos, v);
            vneg = fminf(vneg, v);
        }
#pragma unroll
        for (int o = 16; o > 0; o >>= 1) {
            const float oa = __shfl_down_sync(0xffffffffu, bestAbs, o);
            const int   oi = __shfl_down_sync(0xffffffffu, bestIdx, o);
            const float ov = __shfl_down_sync(0xffffffffu, bestVal, o);
            if (oa > bestAbs || (oa == bestAbs && oi < bestIdx)) {
                bestAbs = oa; bestIdx = oi; bestVal = ov;
            }
            vpos = fmaxf(vpos, __shfl_down_sync(0xffffffffu, vpos, o));
            vneg = fminf(vneg, __shfl_down_sync(0xffffffffu, vneg, o));
        }

        if (lane == 0) {
            const int   ch    = c0 + cc;
            const float vside = (bestVal >= 0.0f) ? vneg : vpos;
            out[(size_t)XCOR_N + ch]           = bestVal;
            out[(size_t)XCOR_N + NCH + ch]     = vside;
            out[(size_t)XCOR_N + 2 * NCH + ch] = (float)(bestIdx - 51) * 0.01f;
        }
    }
}

// ---------------------------------------------------------------------------
// kernel_launch: inputs: data1 (f32, NC*NT), data2 (f32, NC*NT), event1,
// event2 (i32, unused by the reference).
// ---------------------------------------------------------------------------
extern "C" void kernel_launch(void* const* d_in, const int* in_sizes, int n_in,
                              void* d_out, int out_size)
{
    const float* data1 = (const float*)d_in[0];
    const float* data2 = (const float*)d_in[1];
    float* out = (float*)d_out;

    xcorr_stage1<<<NCH, T1, SMEM1>>>(data1, data2);
    xcorr_stage2<<<NCH / CPB, 128>>>(out);
}

// round 15
// speedup vs baseline: 1.1833x; 1.0009x over previous
#include <cuda_runtime.h>

// Problem constants
#define NCH   8192
#define NTT   4096
#define NLAGS 103
#define RAWS  112
#define XCOR_N (NCH * NLAGS)

// Stage-1: 4 warps/block; exact lag split {26,26,26,25}, bases {0,26,52,78}.
// d1 stored UNshifted at float offset 64 => d1pad[x] = a_sm[x + 13].
// Per-slot aligned window base B=(lb+13)&~3, compile-time offset OFF=(lb+13)&3.
#define T1     128
#define A_OFF  64            // where d1[0] lands in a_sm (16B aligned)
#define A_SZ   4224          // covers max read index 4211
#define SMEM1  ((A_SZ + NTT) * 4)

// Raw xcorr scratch: 8192 x 112 f32 (~3.67 MB, L2-resident)
__device__ float g_raw[(size_t)NCH * RAWS];

// ---------------------------------------------------------------------------
// Per-warp correlation: L lags, window offset OFF from the aligned base a_al.
// Lane handles 4 consecutive t per iter; 32 iters cover 4096 t.
// acc[j] = sum_t a_al[t + OFF + j + k] * b[t + k]  (k = 0..3 within the iter)
// ---------------------------------------------------------------------------
template<int L, int OFF>
__device__ __forceinline__ void corr_warp(const float* __restrict__ a_al,
                                          const float* __restrict__ b_sm,
                                          int lane,
                                          float* __restrict__ outRow)
{
    constexpr int NV = (OFF + L + 3 + 3) / 4;   // float4 loads covering window

    float acc[L];
#pragma unroll
    for (int j = 0; j < L; ++j) acc[j] = 0.0f;

#pragma unroll 1
    for (int it = 0; it < 32; ++it) {
        const int t0 = it * 128 + lane * 4;

        float aw[NV * 4];
#pragma unroll
        for (int v = 0; v < NV; ++v) {
            const float4 w = *reinterpret_cast<const float4*>(a_al + t0 + 4 * v);
            aw[4 * v + 0] = w.x; aw[4 * v + 1] = w.y;
            aw[4 * v + 2] = w.z; aw[4 * v + 3] = w.w;
        }
        const float4 b4 = *reinterpret_cast<const float4*>(b_sm + t0);
        float bv[4];
        bv[0] = b4.x; bv[1] = b4.y; bv[2] = b4.z; bv[3] = b4.w;

#pragma unroll
        for (int k = 0; k < 4; ++k) {
#pragma unroll
            for (int j = 0; j < L; ++j) {
                acc[j] = fmaf(aw[OFF + j + k], bv[k], acc[j]);
            }
        }
    }

    // Lane reduction over t; lane 0 writes L lags.
#pragma unroll
    for (int j = 0; j < L; ++j) {
#pragma unroll
        for (int o = 16; o > 0; o >>= 1)
            acc[j] += __shfl_xor_sync(0xffffffffu, acc[j], o);
    }
    if (lane == 0) {
#pragma unroll
        for (int j = 0; j < L; ++j) outRow[j] = acc[j];
    }
}

// ---------------------------------------------------------------------------
// Stage 1: R[c][l] = sum_t d1pad[t+l] * d2[t], l in [0,103), with
// d1pad[x] = d1[x-51] (zero outside). One block per channel, 128 threads.
// Slot -> (lag base lb, L, aligned base B=(lb+13)&~3, OFF=(lb+13)&3):
//   0: lb=0,  L=26, B=12, OFF=1
//   1: lb=26, L=26, B=36, OFF=3
//   2: lb=52, L=26, B=64, OFF=1
//   3: lb=78, L=25, B=88, OFF=3
// ---------------------------------------------------------------------------
__global__ __launch_bounds__(T1, 6)
void xcorr_stage1(const float* __restrict__ d1, const float* __restrict__ d2)
{
    extern __shared__ __align__(16) float sm[];
    float* a_sm = sm;            // [A_SZ]; d1 at [A_OFF, A_OFF+NTT)
    float* b_sm = sm + A_SZ;     // [NTT]

    const int c   = blockIdx.x;
    const int tid = threadIdx.x;

    const float* __restrict__ r1 = d1 + (size_t)c * NTT;
    const float* __restrict__ r2 = d2 + (size_t)c * NTT;

    // Zero pads: [0, A_OFF) and [A_OFF+NTT, A_SZ)
    for (int i = tid; i < A_OFF / 4; i += T1)
        reinterpret_cast<float4*>(a_sm)[i] = make_float4(0.f, 0.f, 0.f, 0.f);
    for (int i = tid; i < (A_SZ - A_OFF - NTT) / 4; i += T1)
        reinterpret_cast<float4*>(a_sm + A_OFF + NTT)[i] = make_float4(0.f, 0.f, 0.f, 0.f);

    // Bulk fill: pure float4 loads and stores (a unshifted at offset 64).
    for (int k = tid; k < NTT / 4; k += T1) {
        reinterpret_cast<float4*>(a_sm + A_OFF)[k] = reinterpret_cast<const float4*>(r1)[k];
        reinterpret_cast<float4*>(b_sm)[k]         = reinterpret_cast<const float4*>(r2)[k];
    }
    __syncthreads();

    const int warp = tid >> 5;
    const int lane = tid & 31;
    // Rotate slot assignment across blocks for SMSP load balance.
    const int slot = (warp + blockIdx.x) & 3;

    float* row = g_raw + (size_t)c * RAWS;
    switch (slot) {
        case 0: corr_warp<26, 1>(a_sm + 12, b_sm, lane, row + 0);  break;
        case 1: corr_warp<26, 3>(a_sm + 36, b_sm, lane, row + 26); break;
        case 2: corr_warp<26, 1>(a_sm + 64, b_sm, lane, row + 52); break;
        default: corr_warp<25, 3>(a_sm + 88, b_sm, lane, row + 78); break;
    }
}

// ---------------------------------------------------------------------------
// Stage 2: moving average over channels (window [c-10, c+9], zero-padded),
// then per-channel argmax|R| / max / min / tmax.
// 4 channels per block (2048 blocks -> deep latency overlap); each thread
// prefetches all 23 halo values (MLP) then slides the sum in registers.
// ---------------------------------------------------------------------------
#define CPB 4
__global__ __launch_bounds__(128)
void xcorr_stage2(float* __restrict__ out)
{
    __shared__ float sh[CPB][NLAGS + 1];
    const int c0  = blockIdx.x * CPB;
    const int tid = threadIdx.x;

    if (tid < NLAGS) {
        float x[CPB + 19];
#pragma unroll
        for (int i = 0; i < CPB + 19; ++i) {
            const int ch = c0 - 10 + i;
            x[i] = (ch >= 0 && ch < NCH) ? g_raw[(size_t)ch * RAWS + tid] : 0.0f;
        }
        float s = 0.0f;
#pragma unroll
        for (int i = 0; i < 20; ++i) s += x[i];
#pragma unroll
        for (int cc = 0; cc < CPB; ++cc) {
            const float m = s * (1.0f / 20.0f);
            sh[cc][tid] = m;
            out[(size_t)(c0 + cc) * NLAGS + tid] = m;
            if (cc + 1 < CPB) s += x[cc + 20] - x[cc];
        }
    }
    __syncthreads();

    const int warp = tid >> 5;
    const int lane = tid & 31;

    // One warp per channel (4 warps, 4 channels).
    {
        const int cc = warp;
        float bestAbs = -1.0f;
        int   bestIdx = 0;
        float bestVal = 0.0f;
        float vpos = -3.402823466e38f;
        float vneg =  3.402823466e38f;

        for (int l = lane; l < NLAGS; l += 32) {
            const float v  = sh[cc][l];
            const float av = fabsf(v);
            if (av > bestAbs) { bestAbs = av; bestIdx = l; bestVal = v; }
            vpos = fmaxf(vpos, v);
            vneg = fminf(vneg, v);
        }
#pragma unroll
        for (int o = 16; o > 0; o >>= 1) {
            const float oa = __shfl_down_sync(0xffffffffu, bestAbs, o);
            const int   oi = __shfl_down_sync(0xffffffffu, bestIdx, o);
            const float ov = __shfl_down_sync(0xffffffffu, bestVal, o);
            if (oa > bestAbs || (oa == bestAbs && oi < bestIdx)) {
                bestAbs = oa; bestIdx = oi; bestVal = ov;
            }
            vpos = fmaxf(vpos, __shfl_down_sync(0xffffffffu, vpos, o));
            vneg = fminf(vneg, __shfl_down_sync(0xffffffffu, vneg, o));
        }

        if (lane == 0) {
            const int   ch    = c0 + cc;
            const float vside = (bestVal >= 0.0f) ? vneg : vpos;
            out[(size_t)XCOR_N + ch]           = bestVal;
            out[(size_t)XCOR_N + NCH + ch]     = vside;
            out[(size_t)XCOR_N + 2 * NCH + ch] = (float)(bestIdx - 51) * 0.01f;
        }
    }
}

// ---------------------------------------------------------------------------
// kernel_launch: inputs: data1 (f32, NC*NT), data2 (f32, NC*NT), event1,
// event2 (i32, unused by the reference).
// ---------------------------------------------------------------------------
extern "C" void kernel_launch(void* const* d_in, const int* in_sizes, int n_in,
                              void* d_out, int out_size)
{
    const float* data1 = (const float*)d_in[0];
    const float* data2 = (const float*)d_in[1];
    float* out = (float*)d_out;

    xcorr_stage1<<<NCH, T1, SMEM1>>>(data1, data2);
    xcorr_stage2<<<NCH / CPB, 128>>>(out);
}

// round 16
// speedup vs baseline: 1.1871x; 1.0032x over previous
#include <cuda_runtime.h>

// Problem constants
#define NCH   8192
#define NTT   4096
#define NLAGS 103
#define RAWS  112
#define XCOR_N (NCH * NLAGS)

// Stage-1: 4 warps/block; exact lag split {26,26,26,25}, bases {0,26,52,78}.
// d1 stored UNshifted at float offset 64 => d1pad[x] = a_sm[x + 13].
// Per-slot aligned window base B=(lb+13)&~3, compile-time offset OFF=(lb+13)&3.
// Scalar FFMA mainloop: measured at the rt=2 FMA-pipe roofline.
#define T1     128
#define A_OFF  64            // where d1[0] lands in a_sm (16B aligned)
#define A_SZ   4224          // covers max read index 4211
#define SMEM1  ((A_SZ + NTT) * 4)

// Raw xcorr scratch: 8192 x 112 f32 (~3.67 MB, L2-resident)
__device__ float g_raw[(size_t)NCH * RAWS];

// ---------------------------------------------------------------------------
// Per-warp correlation: L lags, window offset OFF from the aligned base a_al.
// Lane handles 4 consecutive t per iter; 32 iters cover 4096 t.
// acc[j] = sum_t a_al[t + OFF + j + k] * b[t + k]  (k = 0..3 within the iter)
// ---------------------------------------------------------------------------
template<int L, int OFF>
__device__ __forceinline__ void corr_warp(const float* __restrict__ a_al,
                                          const float* __restrict__ b_sm,
                                          int lane,
                                          float* __restrict__ outRow)
{
    constexpr int NV = (OFF + L + 3 + 3) / 4;   // float4 loads covering window

    float acc[L];
#pragma unroll
    for (int j = 0; j < L; ++j) acc[j] = 0.0f;

#pragma unroll 1
    for (int it = 0; it < 32; ++it) {
        const int t0 = it * 128 + lane * 4;

        float aw[NV * 4];
#pragma unroll
        for (int v = 0; v < NV; ++v) {
            const float4 w = *reinterpret_cast<const float4*>(a_al + t0 + 4 * v);
            aw[4 * v + 0] = w.x; aw[4 * v + 1] = w.y;
            aw[4 * v + 2] = w.z; aw[4 * v + 3] = w.w;
        }
        const float4 b4 = *reinterpret_cast<const float4*>(b_sm + t0);
        float bv[4];
        bv[0] = b4.x; bv[1] = b4.y; bv[2] = b4.z; bv[3] = b4.w;

#pragma unroll
        for (int k = 0; k < 4; ++k) {
#pragma unroll
            for (int j = 0; j < L; ++j) {
                acc[j] = fmaf(aw[OFF + j + k], bv[k], acc[j]);
            }
        }
    }

    // Lane reduction over t; lane 0 writes L lags.
#pragma unroll
    for (int j = 0; j < L; ++j) {
#pragma unroll
        for (int o = 16; o > 0; o >>= 1)
            acc[j] += __shfl_xor_sync(0xffffffffu, acc[j], o);
    }
    if (lane == 0) {
#pragma unroll
        for (int j = 0; j < L; ++j) outRow[j] = acc[j];
    }
}

// ---------------------------------------------------------------------------
// Stage 1: R[c][l] = sum_t d1pad[t+l] * d2[t], l in [0,103), with
// d1pad[x] = d1[x-51] (zero outside). One block per channel, 128 threads.
// Slot -> (lag base lb, L, aligned base B=(lb+13)&~3, OFF=(lb+13)&3):
//   0: lb=0,  L=26, B=12, OFF=1
//   1: lb=26, L=26, B=36, OFF=3
//   2: lb=52, L=26, B=64, OFF=1
//   3: lb=78, L=25, B=88, OFF=3
// ---------------------------------------------------------------------------
__global__ __launch_bounds__(T1, 6)
void xcorr_stage1(const float* __restrict__ d1, const float* __restrict__ d2)
{
    extern __shared__ __align__(16) float sm[];
    float* a_sm = sm;            // [A_SZ]; d1 at [A_OFF, A_OFF+NTT)
    float* b_sm = sm + A_SZ;     // [NTT]

    const int c   = blockIdx.x;
    const int tid = threadIdx.x;

    const float* __restrict__ r1 = d1 + (size_t)c * NTT;
    const float* __restrict__ r2 = d2 + (size_t)c * NTT;

    // Zero pads: [0, A_OFF) and [A_OFF+NTT, A_SZ)
    for (int i = tid; i < A_OFF / 4; i += T1)
        reinterpret_cast<float4*>(a_sm)[i] = make_float4(0.f, 0.f, 0.f, 0.f);
    for (int i = tid; i < (A_SZ - A_OFF - NTT) / 4; i += T1)
        reinterpret_cast<float4*>(a_sm + A_OFF + NTT)[i] = make_float4(0.f, 0.f, 0.f, 0.f);

    // Bulk fill: pure float4 loads and stores (a unshifted at offset 64).
    for (int k = tid; k < NTT / 4; k += T1) {
        reinterpret_cast<float4*>(a_sm + A_OFF)[k] = reinterpret_cast<const float4*>(r1)[k];
        reinterpret_cast<float4*>(b_sm)[k]         = reinterpret_cast<const float4*>(r2)[k];
    }
    __syncthreads();

    const int warp = tid >> 5;
    const int lane = tid & 31;
    // Rotate slot assignment across blocks for SMSP load balance.
    const int slot = (warp + blockIdx.x) & 3;

    float* row = g_raw + (size_t)c * RAWS;
    switch (slot) {
        case 0: corr_warp<26, 1>(a_sm + 12, b_sm, lane, row + 0);  break;
        case 1: corr_warp<26, 3>(a_sm + 36, b_sm, lane, row + 26); break;
        case 2: corr_warp<26, 1>(a_sm + 64, b_sm, lane, row + 52); break;
        default: corr_warp<25, 3>(a_sm + 88, b_sm, lane, row + 78); break;
    }
}

// ---------------------------------------------------------------------------
// Stage 2: moving average over channels (window [c-10, c+9], zero-padded),
// then per-channel argmax|R| / max / min / tmax.
// 8 channels per block (measured optimum of CPB = 4/8/16 sweep); each thread
// prefetches all 27 halo values (MLP) then slides the sum in registers.
// ---------------------------------------------------------------------------
#define CPB 8
__global__ __launch_bounds__(128)
void xcorr_stage2(float* __restrict__ out)
{
    __shared__ float sh[CPB][NLAGS + 1];
    const int c0  = blockIdx.x * CPB;
    const int tid = threadIdx.x;

    if (tid < NLAGS) {
        float x[CPB + 19];
#pragma unroll
        for (int i = 0; i < CPB + 19; ++i) {
            const int ch = c0 - 10 + i;
            x[i] = (ch >= 0 && ch < NCH) ? g_raw[(size_t)ch * RAWS + tid] : 0.0f;
        }
        float s = 0.0f;
#pragma unroll
        for (int i = 0; i < 20; ++i) s += x[i];
#pragma unroll
        for (int cc = 0; cc < CPB; ++cc) {
            const float m = s * (1.0f / 20.0f);
            sh[cc][tid] = m;
            out[(size_t)(c0 + cc) * NLAGS + tid] = m;
            if (cc + 1 < CPB) s += x[cc + 20] - x[cc];
        }
    }
    __syncthreads();

    const int warp = tid >> 5;
    const int lane = tid & 31;

    for (int cc = warp; cc < CPB; cc += 4) {
        float bestAbs = -1.0f;
        int   bestIdx = 0;
        float bestVal = 0.0f;
        float vpos = -3.402823466e38f;
        float vneg =  3.402823466e38f;

        for (int l = lane; l < NLAGS; l += 32) {
            const float v  = sh[cc][l];
            const float av = fabsf(v);
            if (av > bestAbs) { bestAbs = av; bestIdx = l; bestVal = v; }
            vpos = fmaxf(vpos, v);
            vneg = fminf(vneg, v);
        }
#pragma unroll
        for (int o = 16; o > 0; o >>= 1) {
            const float oa = __shfl_down_sync(0xffffffffu, bestAbs, o);
            const int   oi = __shfl_down_sync(0xffffffffu, bestIdx, o);
            const float ov = __shfl_down_sync(0xffffffffu, bestVal, o);
            if (oa > bestAbs || (oa == bestAbs && oi < bestIdx)) {
                bestAbs = oa; bestIdx = oi; bestVal = ov;
            }
            vpos = fmaxf(vpos, __shfl_down_sync(0xffffffffu, vpos, o));
            vneg = fminf(vneg, __shfl_down_sync(0xffffffffu, vneg, o));
        }

        if (lane == 0) {
            const int   ch    = c0 + cc;
            const float vside = (bestVal >= 0.0f) ? vneg : vpos;
            out[(size_t)XCOR_N + ch]           = bestVal;
            out[(size_t)XCOR_N + NCH + ch]     = vside;
            out[(size_t)XCOR_N + 2 * NCH + ch] = (float)(bestIdx - 51) * 0.01f;
        }
    }
}

// ---------------------------------------------------------------------------
// kernel_launch: inputs: data1 (f32, NC*NT), data2 (f32, NC*NT), event1,
// event2 (i32, unused by the reference).
// ---------------------------------------------------------------------------
extern "C" void kernel_launch(void* const* d_in, const int* in_sizes, int n_in,
                              void* d_out, int out_size)
{
    const float* data1 = (const float*)d_in[0];
    const float* data2 = (const float*)d_in[1];
    float* out = (float*)d_out;

    xcorr_stage1<<<NCH, T1, SMEM1>>>(data1, data2);
    xcorr_stage2<<<NCH / CPB, 128>>>(out);
}